// round 10
// baseline (speedup 1.0000x reference)
#include <cuda_runtime.h>
#include <cuda_fp16.h>
#include <cstdint>

// ============================================================================
// CIN via mma.sync m16n8k16 FP16, 3-term hi/lo split, x-scale hoisted out.
// R10: CTA tile 64m x 128n, 2 CTAs/SM (512-CTA grid -> 1.73 waves, occ-2
// latency hiding). Per i: t = H @ W_i (A split once per tile), hacc += x_i * t.
// ============================================================================

#define CIN_B   2048
#define CIN_F0  64
#define CIN_D   16
#define CIN_FN  128
#define CIN_M   (CIN_B * CIN_D)   // 32768

// Per 32-K chunk: [hi 16 kpairs x 136 u32][lo 16 x 136] = 4352 u32
#define CH_U32  4352
#define CH_HALF 2176

// Device scratch
__device__ float    g_xT[CIN_M * CIN_F0];                    // 8 MB
__device__ uint32_t g_wp[(128 + 256 + 256) * CH_U32];        // 11.1 MB fp16 pairs
__device__ float    g_h [3 * (size_t)CIN_M * CIN_FN];        // 48 MB

// ---------------------------------------------------------------------------
__device__ __forceinline__ uint32_t smem_u32(const void* p) {
    uint32_t a;
    asm("{ .reg .u64 t; cvta.to.shared.u64 t, %1; cvt.u32.u64 %0, t; }" : "=r"(a) : "l"(p));
    return a;
}
__device__ __forceinline__ void cp16(uint32_t dst, const void* src) {
    asm volatile("cp.async.cg.shared.global [%0], [%1], 16;" :: "r"(dst), "l"(src) : "memory");
}
__device__ __forceinline__ void cp_commit() {
    asm volatile("cp.async.commit_group;" ::: "memory");
}
__device__ __forceinline__ void cp_wait1() {
    asm volatile("cp.async.wait_group 1;" ::: "memory");
}
__device__ __forceinline__ void cp_wait0() {
    asm volatile("cp.async.wait_group 0;" ::: "memory");
}
__device__ __forceinline__ void mma_f16(float& d0, float& d1, float& d2, float& d3,
                                        uint32_t a0, uint32_t a1, uint32_t a2, uint32_t a3,
                                        uint32_t b0, uint32_t b1) {
    asm volatile(
        "mma.sync.aligned.m16n8k16.row.col.f32.f16.f16.f32 "
        "{%0,%1,%2,%3}, {%4,%5,%6,%7}, {%8,%9}, {%0,%1,%2,%3};"
        : "+f"(d0), "+f"(d1), "+f"(d2), "+f"(d3)
        : "r"(a0), "r"(a1), "r"(a2), "r"(a3), "r"(b0), "r"(b1));
}
__device__ __forceinline__ void pack_split(float v0, float v1, uint32_t& hi, uint32_t& lo) {
    __half2 h = __floats2half2_rn(v0, v1);
    float2 back = __half22float2(h);
    __half2 l = __floats2half2_rn(v0 - back.x, v1 - back.y);
    hi = *reinterpret_cast<uint32_t*>(&h);
    lo = *reinterpret_cast<uint32_t*>(&l);
}

// ---------------------------------------------------------------------------
// Prep: x [B, F0, D] -> xT [(b*16+d), 64]
__global__ void k_xT(const float* __restrict__ x, float* __restrict__ xT) {
    int o = blockIdx.x * 256 + threadIdx.x;
    if (o >= CIN_M * CIN_F0) return;
    int i = o & 63;
    int m = o >> 6;
    int b = m >> 4;
    int d = m & 15;
    xT[o] = x[(b * CIN_F0 + i) * CIN_D + d];
}

// Prep: W -> fp16 hi/lo pairs per 32-K chunk.
__global__ void k_wp(const float* __restrict__ W, uint32_t* __restrict__ dst, int Fi) {
    int CPI = Fi >> 5;
    int total = (CIN_F0 * CPI) * 16 * 128;
    for (int o = blockIdx.x * 256 + threadIdx.x; o < total; o += gridDim.x * 256) {
        int n = o & 127;
        int p = (o >> 7) & 15;
        int s = o >> 11;
        int i = s / CPI;
        int jc = s - i * CPI;
        int j0 = jc * 32 + 2 * p;
        float v0 = W[(i * Fi + j0) * 128 + n];
        float v1 = W[(i * Fi + j0 + 1) * 128 + n];
        uint32_t hi, lo;
        pack_split(v0, v1, hi, lo);
        uint32_t base = (uint32_t)s * CH_U32 + p * 136 + n;
        dst[base] = hi;
        dst[base + CH_HALF] = lo;
    }
}

// ---------------------------------------------------------------------------
// Main GEMM. 256 threads = 8 warps (2 wm x 4 wn), CTA tile 64m x 128n.
// Warp tile 32m x 32n. K' in chunks of 32 (2 k16 steps).
// SMEM:
//   HsHi [FI/2 kpairs][72] u32 (stride 72 = 8 mod 32: conflict-free reads)
//   HsLo [FI/2][72] u32
//   xs   [64][68] fp32
//   Bp   [3 bufs][CH_U32] u32
template <int FI>
__global__ __launch_bounds__(256, 2) void cin_mma(
    const float* __restrict__ H,
    const uint32_t* __restrict__ Wp,
    const float* __restrict__ xT,
    float* __restrict__ Hout) {
    extern __shared__ char smem[];
    constexpr int KP = FI / 2;
    constexpr int HS_U32 = KP * 72;
    constexpr int XB = 2 * HS_U32 * 4;             // xs byte offset
    constexpr int BB = XB + 64 * 68 * 4;           // B byte offset
    constexpr int CPI = FI / 32;
    constexpr int NC = CIN_F0 * CPI;

    uint32_t* HsHi = reinterpret_cast<uint32_t*>(smem);
    uint32_t* HsLo = HsHi + HS_U32;
    float* xs = reinterpret_cast<float*>(smem + XB);
    uint32_t* Bp = reinterpret_cast<uint32_t*>(smem + BB);
    const uint32_t bs_u32 = smem_u32(Bp);

    const int tid = threadIdx.x;
    const int lane = tid & 31;
    const int wid = tid >> 5;
    const int g = lane >> 2;     // 0..7
    const int c = lane & 3;      // 0..3
    const int wm = wid >> 2;     // 0..1
    const int wn = wid & 3;      // 0..3
    const int m0 = blockIdx.x * 64;
    const int row0 = wm * 32 + g;   // + mt*16 (+8)

    // Build Hs hi/lo (once per tile)
    for (int idx = tid; idx < 64 * KP; idx += 256) {
        int p = idx % KP;
        int m = idx / KP;
        float2 v = *reinterpret_cast<const float2*>(H + (size_t)(m0 + m) * FI + 2 * p);
        uint32_t hi, lo;
        pack_split(v.x, v.y, hi, lo);
        HsHi[p * 72 + m] = hi;
        HsLo[p * 72 + m] = lo;
    }
    // Load x tile
    {
        const float4* Xg = reinterpret_cast<const float4*>(xT + (size_t)m0 * 64);
        for (int idx = tid; idx < 64 * 16; idx += 256) {
            int m = idx >> 4;
            int seg = idx & 15;
            *reinterpret_cast<float4*>(xs + m * 68 + seg * 4) = Xg[idx];
        }
    }

    // Prefetch chunks 0 and 1 (ring depth 3, 2 in flight)
#pragma unroll
    for (int pc = 0; pc < 2; ++pc) {
        const uint32_t* src = Wp + (size_t)pc * CH_U32;
        uint32_t dstb = bs_u32 + (uint32_t)(pc * CH_U32) * 4;
#pragma unroll
        for (int q = 0; q < 5; ++q) {
            int idx = tid + 256 * q;
            if (idx < CH_U32 / 4) cp16(dstb + (uint32_t)idx * 16, src + idx * 4);
        }
        cp_commit();
    }

    float hacc[2][4][4];
#pragma unroll
    for (int mt = 0; mt < 2; mt++)
#pragma unroll
        for (int nt = 0; nt < 4; nt++)
#pragma unroll
            for (int q = 0; q < 4; q++) hacc[mt][nt][q] = 0.f;

    int s = 0;
    for (int i = 0; i < CIN_F0; ++i) {
        float t[2][4][4];
#pragma unroll
        for (int mt = 0; mt < 2; mt++)
#pragma unroll
            for (int nt = 0; nt < 4; nt++)
#pragma unroll
                for (int q = 0; q < 4; q++) t[mt][nt][q] = 0.f;

#pragma unroll
        for (int jc = 0; jc < CPI; ++jc, ++s) {
            if (s + 1 < NC) cp_wait1(); else cp_wait0();
            __syncthreads();

            const int rbuf = s % 3;
            const uint32_t* Bc = Bp + rbuf * CH_U32;

#pragma unroll
            for (int ks = 0; ks < 2; ++ks) {
                const int kp0 = jc * 16 + ks * 8 + c;
                uint32_t ah[2][4], al[2][4];
#pragma unroll
                for (int mt = 0; mt < 2; mt++) {
                    int r = row0 + mt * 16;
                    ah[mt][0] = HsHi[kp0 * 72 + r];
                    ah[mt][1] = HsHi[kp0 * 72 + r + 8];
                    ah[mt][2] = HsHi[(kp0 + 4) * 72 + r];
                    ah[mt][3] = HsHi[(kp0 + 4) * 72 + r + 8];
                    al[mt][0] = HsLo[kp0 * 72 + r];
                    al[mt][1] = HsLo[kp0 * 72 + r + 8];
                    al[mt][2] = HsLo[(kp0 + 4) * 72 + r];
                    al[mt][3] = HsLo[(kp0 + 4) * 72 + r + 8];
                }
                const int p0 = (ks * 8 + c) * 136;
                const int p1 = p0 + 4 * 136;
#pragma unroll
                for (int nt = 0; nt < 4; ++nt) {
                    int ncol = wn * 32 + nt * 8 + g;
                    uint32_t b0h = Bc[p0 + ncol];
                    uint32_t b1h = Bc[p1 + ncol];
                    uint32_t b0l = Bc[CH_HALF + p0 + ncol];
                    uint32_t b1l = Bc[CH_HALF + p1 + ncol];
#pragma unroll
                    for (int mt = 0; mt < 2; mt++) {
                        mma_f16(t[mt][nt][0], t[mt][nt][1], t[mt][nt][2], t[mt][nt][3],
                                ah[mt][0], ah[mt][1], ah[mt][2], ah[mt][3], b0h, b1h);
                        mma_f16(t[mt][nt][0], t[mt][nt][1], t[mt][nt][2], t[mt][nt][3],
                                ah[mt][0], ah[mt][1], ah[mt][2], ah[mt][3], b0l, b1l);
                        mma_f16(t[mt][nt][0], t[mt][nt][1], t[mt][nt][2], t[mt][nt][3],
                                al[mt][0], al[mt][1], al[mt][2], al[mt][3], b0h, b1h);
                    }
                }
            }

            if (s + 2 < NC) {
                const uint32_t* src = Wp + (size_t)(s + 2) * CH_U32;
                uint32_t dstb = bs_u32 + (uint32_t)(((s + 2) % 3) * CH_U32) * 4;
#pragma unroll
                for (int q = 0; q < 5; ++q) {
                    int idx = tid + 256 * q;
                    if (idx < CH_U32 / 4) cp16(dstb + (uint32_t)idx * 16, src + idx * 4);
                }
                cp_commit();
            }
        }

        // Fold t into hacc with exact fp32 x-scale
        float xv0 = xs[row0 * 68 + i];
        float xv1 = xs[(row0 + 8) * 68 + i];
        float xv2 = xs[(row0 + 16) * 68 + i];
        float xv3 = xs[(row0 + 24) * 68 + i];
#pragma unroll
        for (int nt = 0; nt < 4; nt++) {
            hacc[0][nt][0] += xv0 * t[0][nt][0];
            hacc[0][nt][1] += xv0 * t[0][nt][1];
            hacc[0][nt][2] += xv1 * t[0][nt][2];
            hacc[0][nt][3] += xv1 * t[0][nt][3];
            hacc[1][nt][0] += xv2 * t[1][nt][0];
            hacc[1][nt][1] += xv2 * t[1][nt][1];
            hacc[1][nt][2] += xv3 * t[1][nt][2];
            hacc[1][nt][3] += xv3 * t[1][nt][3];
        }
    }

    // Epilogue
#pragma unroll
    for (int mt = 0; mt < 2; mt++) {
        int row = m0 + row0 + mt * 16;
#pragma unroll
        for (int nt = 0; nt < 4; nt++) {
            int col = wn * 32 + nt * 8 + 2 * c;
            float2 v0 = make_float2(hacc[mt][nt][0], hacc[mt][nt][1]);
            float2 v1 = make_float2(hacc[mt][nt][2], hacc[mt][nt][3]);
            *reinterpret_cast<float2*>(Hout + (size_t)row * CIN_FN + col) = v0;
            *reinterpret_cast<float2*>(Hout + (size_t)(row + 8) * CIN_FN + col) = v1;
        }
    }
}

// ---------------------------------------------------------------------------
__global__ void k_reduce(const float* __restrict__ h, float* __restrict__ out) {
    int b = blockIdx.x;
    int l = blockIdx.y;
    int n = threadIdx.x;
    const float* hp = h + (size_t)l * CIN_M * CIN_FN + (size_t)(b * CIN_D) * CIN_FN + n;
    float s = 0.f;
#pragma unroll
    for (int d = 0; d < CIN_D; ++d) s += hp[d * CIN_FN];
    out[b * 384 + l * 128 + n] = s;
}

// ---------------------------------------------------------------------------
extern "C" void kernel_launch(void* const* d_in, const int* in_sizes, int n_in,
                              void* d_out, int out_size) {
    const float* x  = (const float*)d_in[0];
    const float* W0 = (const float*)d_in[1];
    const float* W1 = (const float*)d_in[2];
    const float* W2 = (const float*)d_in[3];
    float* out = (float*)d_out;

    float *xT, *h;
    uint32_t* wp;
    cudaGetSymbolAddress((void**)&xT, g_xT);
    cudaGetSymbolAddress((void**)&wp, g_wp);
    cudaGetSymbolAddress((void**)&h,  g_h);

    uint32_t* wp_0 = wp;
    uint32_t* wp_1 = wp + (size_t)128 * CH_U32;
    uint32_t* wp_2 = wp_1 + (size_t)256 * CH_U32;
    float* h0 = h;
    float* h1 = h + (size_t)CIN_M * CIN_FN;
    float* h2 = h + (size_t)2 * CIN_M * CIN_FN;

    // SMEM (bytes): 2*Hs + xs + 3 B bufs
    const int smem64  = (2 * 32 * 72 + 64 * 68) * 4 + 3 * CH_U32 * 4;  // 88,064
    const int smem128 = (2 * 64 * 72 + 64 * 68) * 4 + 3 * CH_U32 * 4;  // 106,496
    cudaFuncSetAttribute(cin_mma<64>,  cudaFuncAttributeMaxDynamicSharedMemorySize, smem64);
    cudaFuncSetAttribute(cin_mma<128>, cudaFuncAttributeMaxDynamicSharedMemorySize, smem128);

    // Prep
    k_xT<<<(CIN_M * CIN_F0 + 255) / 256, 256>>>(x, xT);
    k_wp<<<2048, 256>>>(W0, wp_0, 64);
    k_wp<<<2048, 256>>>(W1, wp_1, 128);
    k_wp<<<2048, 256>>>(W2, wp_2, 128);

    // 3 CIN layers (grid = M/64 = 512 CTAs, 2 CTAs/SM)
    cin_mma<64> <<<CIN_M / 64, 256, smem64 >>>(xT, wp_0, xT, h0);
    cin_mma<128><<<CIN_M / 64, 256, smem128>>>(h0, wp_1, xT, h1);
    cin_mma<128><<<CIN_M / 64, 256, smem128>>>(h1, wp_2, xT, h2);

    // Final d-reduction + concat
    k_reduce<<<dim3(CIN_B, 3), 128>>>(h, out);
}

// round 11
// speedup vs baseline: 1.1005x; 1.1005x over previous
#include <cuda_runtime.h>
#include <cuda_fp16.h>
#include <cstdint>

// ============================================================================
// CIN via mma.sync m16n8k16 FP16, 3-term hi/lo split, x-scale hoisted out.
// R11: back to 128m x 128n tile (R9), but B chunks stream via ONE
// cp.async.bulk + mbarrier per chunk instead of 1088 cp.async (LDGSTS rt=8
// made R9 issue-bound at 2176 cyc/SMSP vs 1536 tensor). Ring of 3 slots.
// ============================================================================

#define CIN_B   2048
#define CIN_F0  64
#define CIN_D   16
#define CIN_FN  128
#define CIN_M   (CIN_B * CIN_D)   // 32768

// Per 32-K chunk: [hi 16 kpairs x 136 u32][lo 16 x 136] = 4352 u32 = 17408 B
#define CH_U32  4352
#define CH_HALF 2176
#define CH_BYTES 17408u

// Device scratch
__device__ float    g_xT[CIN_M * CIN_F0];                    // 8 MB
__device__ uint32_t g_wp[(128 + 256 + 256) * CH_U32];        // 11.1 MB fp16 pairs
__device__ float    g_h [3 * (size_t)CIN_M * CIN_FN];        // 48 MB

// ---------------------------------------------------------------------------
__device__ __forceinline__ uint32_t smem_u32(const void* p) {
    uint32_t a;
    asm("{ .reg .u64 t; cvta.to.shared.u64 t, %1; cvt.u32.u64 %0, t; }" : "=r"(a) : "l"(p));
    return a;
}
__device__ __forceinline__ void mbar_init(uint32_t mbar, uint32_t cnt) {
    asm volatile("mbarrier.init.shared.b64 [%0], %1;" :: "r"(mbar), "r"(cnt) : "memory");
}
__device__ __forceinline__ void mbar_expect_tx(uint32_t mbar, uint32_t bytes) {
    asm volatile("mbarrier.arrive.expect_tx.shared.b64 _, [%0], %1;"
                 :: "r"(mbar), "r"(bytes) : "memory");
}
__device__ __forceinline__ void mbar_wait(uint32_t mbar, uint32_t parity) {
    uint32_t done = 0;
    while (!done) {
        asm volatile(
            "{\n\t.reg .pred p;\n\t"
            "mbarrier.try_wait.parity.shared.b64 p, [%1], %2;\n\t"
            "selp.b32 %0, 1, 0, p;\n\t}"
            : "=r"(done) : "r"(mbar), "r"(parity) : "memory");
    }
}
__device__ __forceinline__ void bulk_g2s(uint32_t dst, const void* src, uint32_t bytes,
                                         uint32_t mbar) {
    asm volatile(
        "cp.async.bulk.shared::cluster.global.mbarrier::complete_tx::bytes "
        "[%0], [%1], %2, [%3];"
        :: "r"(dst), "l"(src), "r"(bytes), "r"(mbar) : "memory");
}
__device__ __forceinline__ void mma_f16(float& d0, float& d1, float& d2, float& d3,
                                        uint32_t a0, uint32_t a1, uint32_t a2, uint32_t a3,
                                        uint32_t b0, uint32_t b1) {
    asm volatile(
        "mma.sync.aligned.m16n8k16.row.col.f32.f16.f16.f32 "
        "{%0,%1,%2,%3}, {%4,%5,%6,%7}, {%8,%9}, {%0,%1,%2,%3};"
        : "+f"(d0), "+f"(d1), "+f"(d2), "+f"(d3)
        : "r"(a0), "r"(a1), "r"(a2), "r"(a3), "r"(b0), "r"(b1));
}
__device__ __forceinline__ void pack_split(float v0, float v1, uint32_t& hi, uint32_t& lo) {
    __half2 h = __floats2half2_rn(v0, v1);
    float2 back = __half22float2(h);
    __half2 l = __floats2half2_rn(v0 - back.x, v1 - back.y);
    hi = *reinterpret_cast<uint32_t*>(&h);
    lo = *reinterpret_cast<uint32_t*>(&l);
}

// ---------------------------------------------------------------------------
// Prep: x [B, F0, D] -> xT [(b*16+d), 64]
__global__ void k_xT(const float* __restrict__ x, float* __restrict__ xT) {
    int o = blockIdx.x * 256 + threadIdx.x;
    if (o >= CIN_M * CIN_F0) return;
    int i = o & 63;
    int m = o >> 6;
    int b = m >> 4;
    int d = m & 15;
    xT[o] = x[(b * CIN_F0 + i) * CIN_D + d];
}

// Prep: W -> fp16 hi/lo pairs per 32-K chunk.
__global__ void k_wp(const float* __restrict__ W, uint32_t* __restrict__ dst, int Fi) {
    int CPI = Fi >> 5;
    int total = (CIN_F0 * CPI) * 16 * 128;
    for (int o = blockIdx.x * 256 + threadIdx.x; o < total; o += gridDim.x * 256) {
        int n = o & 127;
        int p = (o >> 7) & 15;
        int s = o >> 11;
        int i = s / CPI;
        int jc = s - i * CPI;
        int j0 = jc * 32 + 2 * p;
        float v0 = W[(i * Fi + j0) * 128 + n];
        float v1 = W[(i * Fi + j0 + 1) * 128 + n];
        uint32_t hi, lo;
        pack_split(v0, v1, hi, lo);
        uint32_t base = (uint32_t)s * CH_U32 + p * 136 + n;
        dst[base] = hi;
        dst[base + CH_HALF] = lo;
    }
}

// ---------------------------------------------------------------------------
// Main GEMM. 256 threads = 8 warps (4 wm x 2 wn), CTA tile 128m x 128n.
// SMEM layout (bytes):
//   [0..64)    mbar[3] (+pad)
//   [64..)     HsHi [FI/2][136] u32 ; HsLo [FI/2][136] u32
//   xs [128][68] fp32
//   Bp [3 slots][CH_U32] u32
template <int FI>
__global__ __launch_bounds__(256, 1) void cin_mma(
    const float* __restrict__ H,
    const uint32_t* __restrict__ Wp,
    const float* __restrict__ xT,
    float* __restrict__ Hout) {
    extern __shared__ char smem[];
    constexpr int KP = FI / 2;
    constexpr int HS_BYTES = KP * 136 * 4;
    constexpr int HB = 64;                         // Hs offset
    constexpr int XB = HB + 2 * HS_BYTES;          // xs offset
    constexpr int BB = XB + 128 * 68 * 4;          // B slots offset
    constexpr int CPI = FI / 32;
    constexpr int NC = CIN_F0 * CPI;

    uint32_t* HsHi = reinterpret_cast<uint32_t*>(smem + HB);
    uint32_t* HsLo = HsHi + KP * 136;
    float* xs = reinterpret_cast<float*>(smem + XB);
    uint32_t* Bp = reinterpret_cast<uint32_t*>(smem + BB);
    const uint32_t sb = smem_u32(smem);
    const uint32_t bs_u32 = sb + BB;

    const int tid = threadIdx.x;
    const int lane = tid & 31;
    const int wid = tid >> 5;
    const int g = lane >> 2;     // 0..7
    const int c = lane & 3;      // 0..3
    const int wm = wid >> 1;     // 0..3
    const int wn = wid & 1;      // 0..1
    const int m0 = blockIdx.x * 128;
    const int row0 = wm * 32 + g;   // + mt*16 (+8)

    // Init mbarriers + prefetch chunks 0,1 (ring of 3 slots, 2 in flight)
    if (tid == 0) {
        mbar_init(sb + 0, 1);
        mbar_init(sb + 8, 1);
        mbar_init(sb + 16, 1);
    }
    __syncthreads();
    if (tid == 0) {
#pragma unroll
        for (int pc = 0; pc < 2; ++pc) {
            mbar_expect_tx(sb + pc * 8, CH_BYTES);
            bulk_g2s(bs_u32 + pc * CH_BYTES, Wp + (size_t)pc * CH_U32, CH_BYTES, sb + pc * 8);
        }
    }

    // Build Hs hi/lo (once per tile)
    for (int idx = tid; idx < 128 * KP; idx += 256) {
        int p = idx % KP;
        int m = idx / KP;
        float2 v = *reinterpret_cast<const float2*>(H + (size_t)(m0 + m) * FI + 2 * p);
        uint32_t hi, lo;
        pack_split(v.x, v.y, hi, lo);
        HsHi[p * 136 + m] = hi;
        HsLo[p * 136 + m] = lo;
    }
    // Load x tile
    {
        const float4* Xg = reinterpret_cast<const float4*>(xT + (size_t)m0 * 64);
        for (int idx = tid; idx < 128 * 16; idx += 256) {
            int m = idx >> 4;
            int seg = idx & 15;
            *reinterpret_cast<float4*>(xs + m * 68 + seg * 4) = Xg[idx];
        }
    }
    __syncthreads();   // Hs/xs ready before MMAs

    float hacc[2][8][4];
#pragma unroll
    for (int mt = 0; mt < 2; mt++)
#pragma unroll
        for (int nt = 0; nt < 8; nt++)
#pragma unroll
            for (int q = 0; q < 4; q++) hacc[mt][nt][q] = 0.f;

    int s = 0;
    for (int i = 0; i < CIN_F0; ++i) {
        float t[2][8][4];
#pragma unroll
        for (int mt = 0; mt < 2; mt++)
#pragma unroll
            for (int nt = 0; nt < 8; nt++)
#pragma unroll
                for (int q = 0; q < 4; q++) t[mt][nt][q] = 0.f;

#pragma unroll
        for (int jc = 0; jc < CPI; ++jc, ++s) {
            const int slot = s % 3;
            // Wait for chunk s data; then barrier so ALL warps are done with
            // chunk s-1 before the producer refills its slot ((s+2)%3=(s-1)%3).
            mbar_wait(sb + slot * 8, (s / 3) & 1);
            __syncthreads();
            if (tid == 0 && s + 2 < NC) {
                const int ns = (s + 2) % 3;
                mbar_expect_tx(sb + ns * 8, CH_BYTES);
                bulk_g2s(bs_u32 + ns * CH_BYTES, Wp + (size_t)(s + 2) * CH_U32,
                         CH_BYTES, sb + ns * 8);
            }

            const uint32_t* Bc = Bp + slot * CH_U32;
#pragma unroll
            for (int ks = 0; ks < 2; ++ks) {
                const int kp0 = jc * 16 + ks * 8 + c;
                uint32_t ah[2][4], al[2][4];
#pragma unroll
                for (int mt = 0; mt < 2; mt++) {
                    int r = row0 + mt * 16;
                    ah[mt][0] = HsHi[kp0 * 136 + r];
                    ah[mt][1] = HsHi[kp0 * 136 + r + 8];
                    ah[mt][2] = HsHi[(kp0 + 4) * 136 + r];
                    ah[mt][3] = HsHi[(kp0 + 4) * 136 + r + 8];
                    al[mt][0] = HsLo[kp0 * 136 + r];
                    al[mt][1] = HsLo[kp0 * 136 + r + 8];
                    al[mt][2] = HsLo[(kp0 + 4) * 136 + r];
                    al[mt][3] = HsLo[(kp0 + 4) * 136 + r + 8];
                }
                const int p0 = (ks * 8 + c) * 136;
                const int p1 = p0 + 4 * 136;
#pragma unroll
                for (int nt = 0; nt < 8; ++nt) {
                    int ncol = wn * 64 + nt * 8 + g;
                    uint32_t b0h = Bc[p0 + ncol];
                    uint32_t b1h = Bc[p1 + ncol];
                    uint32_t b0l = Bc[CH_HALF + p0 + ncol];
                    uint32_t b1l = Bc[CH_HALF + p1 + ncol];
#pragma unroll
                    for (int mt = 0; mt < 2; mt++) {
                        mma_f16(t[mt][nt][0], t[mt][nt][1], t[mt][nt][2], t[mt][nt][3],
                                ah[mt][0], ah[mt][1], ah[mt][2], ah[mt][3], b0h, b1h);
                        mma_f16(t[mt][nt][0], t[mt][nt][1], t[mt][nt][2], t[mt][nt][3],
                                ah[mt][0], ah[mt][1], ah[mt][2], ah[mt][3], b0l, b1l);
                        mma_f16(t[mt][nt][0], t[mt][nt][1], t[mt][nt][2], t[mt][nt][3],
                                al[mt][0], al[mt][1], al[mt][2], al[mt][3], b0h, b1h);
                    }
                }
            }
        }

        // Fold t into hacc with exact fp32 x-scale
        float xv0 = xs[row0 * 68 + i];
        float xv1 = xs[(row0 + 8) * 68 + i];
        float xv2 = xs[(row0 + 16) * 68 + i];
        float xv3 = xs[(row0 + 24) * 68 + i];
#pragma unroll
        for (int nt = 0; nt < 8; nt++) {
            hacc[0][nt][0] += xv0 * t[0][nt][0];
            hacc[0][nt][1] += xv0 * t[0][nt][1];
            hacc[0][nt][2] += xv1 * t[0][nt][2];
            hacc[0][nt][3] += xv1 * t[0][nt][3];
            hacc[1][nt][0] += xv2 * t[1][nt][0];
            hacc[1][nt][1] += xv2 * t[1][nt][1];
            hacc[1][nt][2] += xv3 * t[1][nt][2];
            hacc[1][nt][3] += xv3 * t[1][nt][3];
        }
    }

    // Epilogue
#pragma unroll
    for (int mt = 0; mt < 2; mt++) {
        int row = m0 + row0 + mt * 16;
#pragma unroll
        for (int nt = 0; nt < 8; nt++) {
            int col = wn * 64 + nt * 8 + 2 * c;
            float2 v0 = make_float2(hacc[mt][nt][0], hacc[mt][nt][1]);
            float2 v1 = make_float2(hacc[mt][nt][2], hacc[mt][nt][3]);
            *reinterpret_cast<float2*>(Hout + (size_t)row * CIN_FN + col) = v0;
            *reinterpret_cast<float2*>(Hout + (size_t)(row + 8) * CIN_FN + col) = v1;
        }
    }
}

// ---------------------------------------------------------------------------
__global__ void k_reduce(const float* __restrict__ h, float* __restrict__ out) {
    int b = blockIdx.x;
    int l = blockIdx.y;
    int n = threadIdx.x;
    const float* hp = h + (size_t)l * CIN_M * CIN_FN + (size_t)(b * CIN_D) * CIN_FN + n;
    float s = 0.f;
#pragma unroll
    for (int d = 0; d < CIN_D; ++d) s += hp[d * CIN_FN];
    out[b * 384 + l * 128 + n] = s;
}

// ---------------------------------------------------------------------------
extern "C" void kernel_launch(void* const* d_in, const int* in_sizes, int n_in,
                              void* d_out, int out_size) {
    const float* x  = (const float*)d_in[0];
    const float* W0 = (const float*)d_in[1];
    const float* W1 = (const float*)d_in[2];
    const float* W2 = (const float*)d_in[3];
    float* out = (float*)d_out;

    float *xT, *h;
    uint32_t* wp;
    cudaGetSymbolAddress((void**)&xT, g_xT);
    cudaGetSymbolAddress((void**)&wp, g_wp);
    cudaGetSymbolAddress((void**)&h,  g_h);

    uint32_t* wp_0 = wp;
    uint32_t* wp_1 = wp + (size_t)128 * CH_U32;
    uint32_t* wp_2 = wp_1 + (size_t)256 * CH_U32;
    float* h0 = h;
    float* h1 = h + (size_t)CIN_M * CIN_FN;
    float* h2 = h + (size_t)2 * CIN_M * CIN_FN;

    // SMEM (bytes): 64 (mbars) + 2*Hs + xs + 3 B slots
    const int smem64  = 64 + (2 * 32 * 136 + 128 * 68) * 4 + 3 * CH_BYTES;  // 121,920
    const int smem128 = 64 + (2 * 64 * 136 + 128 * 68) * 4 + 3 * CH_BYTES;  // 156,736
    cudaFuncSetAttribute(cin_mma<64>,  cudaFuncAttributeMaxDynamicSharedMemorySize, smem64);
    cudaFuncSetAttribute(cin_mma<128>, cudaFuncAttributeMaxDynamicSharedMemorySize, smem128);

    // Prep
    k_xT<<<(CIN_M * CIN_F0 + 255) / 256, 256>>>(x, xT);
    k_wp<<<2048, 256>>>(W0, wp_0, 64);
    k_wp<<<2048, 256>>>(W1, wp_1, 128);
    k_wp<<<2048, 256>>>(W2, wp_2, 128);

    // 3 CIN layers (grid = M/128 = 256 CTAs)
    cin_mma<64> <<<CIN_M / 128, 256, smem64 >>>(xT, wp_0, xT, h0);
    cin_mma<128><<<CIN_M / 128, 256, smem128>>>(h0, wp_1, xT, h1);
    cin_mma<128><<<CIN_M / 128, 256, smem128>>>(h1, wp_2, xT, h2);

    // Final d-reduction + concat
    k_reduce<<<dim3(CIN_B, 3), 128>>>(h, out);
}

// round 12
// speedup vs baseline: 1.1325x; 1.0291x over previous
#include <cuda_runtime.h>
#include <cuda_fp16.h>
#include <cstdint>

// ============================================================================
// CIN fully fused: ONE kernel runs all 3 layers + d-reduction per 128-row tile.
// mma.sync m16n8k16 FP16, 3-term hi/lo split, x-scale folded in fp32 per i.
// B streams via cp.async.bulk + mbarrier, ring of 3, continuous across layers.
// h intermediates never touch gmem (register -> SMEM repack at layer bounds).
// ============================================================================

#define CIN_B   2048
#define CIN_F0  64
#define CIN_D   16
#define CIN_FN  128
#define CIN_M   (CIN_B * CIN_D)   // 32768

#define CH_U32  4352
#define CH_HALF 2176
#define CH_BYTES 17408u
#define TOTAL_CHUNKS 640          // 128 (l0) + 256 (l1) + 256 (l2)

// Device scratch
__device__ float    g_xT[CIN_M * CIN_F0];                    // 8 MB
__device__ uint32_t g_wp[(128 + 256 + 256) * CH_U32];        // 11.1 MB fp16 pairs

// ---------------------------------------------------------------------------
__device__ __forceinline__ uint32_t smem_u32(const void* p) {
    uint32_t a;
    asm("{ .reg .u64 t; cvta.to.shared.u64 t, %1; cvt.u32.u64 %0, t; }" : "=r"(a) : "l"(p));
    return a;
}
__device__ __forceinline__ void mbar_init(uint32_t mbar, uint32_t cnt) {
    asm volatile("mbarrier.init.shared.b64 [%0], %1;" :: "r"(mbar), "r"(cnt) : "memory");
}
__device__ __forceinline__ void mbar_expect_tx(uint32_t mbar, uint32_t bytes) {
    asm volatile("mbarrier.arrive.expect_tx.shared.b64 _, [%0], %1;"
                 :: "r"(mbar), "r"(bytes) : "memory");
}
__device__ __forceinline__ void mbar_wait(uint32_t mbar, uint32_t parity) {
    uint32_t done = 0;
    while (!done) {
        asm volatile(
            "{\n\t.reg .pred p;\n\t"
            "mbarrier.try_wait.parity.shared.b64 p, [%1], %2;\n\t"
            "selp.b32 %0, 1, 0, p;\n\t}"
            : "=r"(done) : "r"(mbar), "r"(parity) : "memory");
    }
}
__device__ __forceinline__ void bulk_g2s(uint32_t dst, const void* src, uint32_t bytes,
                                         uint32_t mbar) {
    asm volatile(
        "cp.async.bulk.shared::cluster.global.mbarrier::complete_tx::bytes "
        "[%0], [%1], %2, [%3];"
        :: "r"(dst), "l"(src), "r"(bytes), "r"(mbar) : "memory");
}
__device__ __forceinline__ void mma_f16(float& d0, float& d1, float& d2, float& d3,
                                        uint32_t a0, uint32_t a1, uint32_t a2, uint32_t a3,
                                        uint32_t b0, uint32_t b1) {
    asm volatile(
        "mma.sync.aligned.m16n8k16.row.col.f32.f16.f16.f32 "
        "{%0,%1,%2,%3}, {%4,%5,%6,%7}, {%8,%9}, {%0,%1,%2,%3};"
        : "+f"(d0), "+f"(d1), "+f"(d2), "+f"(d3)
        : "r"(a0), "r"(a1), "r"(a2), "r"(a3), "r"(b0), "r"(b1));
}
__device__ __forceinline__ void pack_split(float v0, float v1, uint32_t& hi, uint32_t& lo) {
    __half2 h = __floats2half2_rn(v0, v1);
    float2 back = __half22float2(h);
    __half2 l = __floats2half2_rn(v0 - back.x, v1 - back.y);
    hi = *reinterpret_cast<uint32_t*>(&h);
    lo = *reinterpret_cast<uint32_t*>(&l);
}
__device__ __forceinline__ const uint32_t* chunk_src(
    const uint32_t* w0, const uint32_t* w1, const uint32_t* w2, int gch) {
    if (gch < 128) return w0 + (size_t)gch * CH_U32;
    if (gch < 384) return w1 + (size_t)(gch - 128) * CH_U32;
    return w2 + (size_t)(gch - 384) * CH_U32;
}

// ---------------------------------------------------------------------------
// Prep: x [B, F0, D] -> xT [(b*16+d), 64]
__global__ void k_xT(const float* __restrict__ x, float* __restrict__ xT) {
    int o = blockIdx.x * 256 + threadIdx.x;
    if (o >= CIN_M * CIN_F0) return;
    int i = o & 63;
    int m = o >> 6;
    int b = m >> 4;
    int d = m & 15;
    xT[o] = x[(b * CIN_F0 + i) * CIN_D + d];
}

// Prep: W -> fp16 hi/lo pairs per 32-K chunk.
__global__ void k_wp(const float* __restrict__ W, uint32_t* __restrict__ dst, int Fi) {
    int CPI = Fi >> 5;
    int total = (CIN_F0 * CPI) * 16 * 128;
    for (int o = blockIdx.x * 256 + threadIdx.x; o < total; o += gridDim.x * 256) {
        int n = o & 127;
        int p = (o >> 7) & 15;
        int s = o >> 11;
        int i = s / CPI;
        int jc = s - i * CPI;
        int j0 = jc * 32 + 2 * p;
        float v0 = W[(i * Fi + j0) * 128 + n];
        float v1 = W[(i * Fi + j0 + 1) * 128 + n];
        uint32_t hi, lo;
        pack_split(v0, v1, hi, lo);
        uint32_t base = (uint32_t)s * CH_U32 + p * 136 + n;
        dst[base] = hi;
        dst[base + CH_HALF] = lo;
    }
}

// ---------------------------------------------------------------------------
// One layer's GEMM mainloop: t = Hs @ W_i chunks, fold into hacc with x_i.
// CPI = FI/32 chunks per i. gch: global chunk counter (continuous ring).
template <int CPI>
__device__ __forceinline__ void run_layer(
    const uint32_t* __restrict__ w0, const uint32_t* __restrict__ w1,
    const uint32_t* __restrict__ w2,
    uint32_t sb, uint32_t bs_u32, const uint32_t* __restrict__ Bp,
    const uint32_t* __restrict__ HsHi, const uint32_t* __restrict__ HsLo,
    const float* __restrict__ xs,
    int& gch, int tid, int row0, int c, int wn,
    float hacc[2][8][4]) {
    for (int i = 0; i < CIN_F0; ++i) {
        float t[2][8][4];
#pragma unroll
        for (int mt = 0; mt < 2; mt++)
#pragma unroll
            for (int nt = 0; nt < 8; nt++)
#pragma unroll
                for (int q = 0; q < 4; q++) t[mt][nt][q] = 0.f;

#pragma unroll
        for (int jc = 0; jc < CPI; ++jc, ++gch) {
            const int slot = gch % 3;
            mbar_wait(sb + slot * 8, (gch / 3) & 1);
            __syncthreads();
            if (tid == 0 && gch + 2 < TOTAL_CHUNKS) {
                const int ns = (gch + 2) % 3;
                mbar_expect_tx(sb + ns * 8, CH_BYTES);
                bulk_g2s(bs_u32 + ns * CH_BYTES, chunk_src(w0, w1, w2, gch + 2),
                         CH_BYTES, sb + ns * 8);
            }

            const uint32_t* Bc = Bp + slot * CH_U32;
#pragma unroll
            for (int ks = 0; ks < 2; ++ks) {
                const int kp0 = jc * 16 + ks * 8 + c;
                uint32_t ah[2][4], al[2][4];
#pragma unroll
                for (int mt = 0; mt < 2; mt++) {
                    int r = row0 + mt * 16;
                    ah[mt][0] = HsHi[kp0 * 136 + r];
                    ah[mt][1] = HsHi[kp0 * 136 + r + 8];
                    ah[mt][2] = HsHi[(kp0 + 4) * 136 + r];
                    ah[mt][3] = HsHi[(kp0 + 4) * 136 + r + 8];
                    al[mt][0] = HsLo[kp0 * 136 + r];
                    al[mt][1] = HsLo[kp0 * 136 + r + 8];
                    al[mt][2] = HsLo[(kp0 + 4) * 136 + r];
                    al[mt][3] = HsLo[(kp0 + 4) * 136 + r + 8];
                }
                const int p0 = (ks * 8 + c) * 136;
                const int p1 = p0 + 4 * 136;
#pragma unroll
                for (int nt = 0; nt < 8; ++nt) {
                    int ncol = wn * 64 + nt * 8 + ((tid & 31) >> 2);
                    uint32_t b0h = Bc[p0 + ncol];
                    uint32_t b1h = Bc[p1 + ncol];
                    uint32_t b0l = Bc[CH_HALF + p0 + ncol];
                    uint32_t b1l = Bc[CH_HALF + p1 + ncol];
                    // Term-interleaved: same-accumulator distance = 2 MMAs
                    mma_f16(t[0][nt][0], t[0][nt][1], t[0][nt][2], t[0][nt][3],
                            ah[0][0], ah[0][1], ah[0][2], ah[0][3], b0h, b1h);
                    mma_f16(t[1][nt][0], t[1][nt][1], t[1][nt][2], t[1][nt][3],
                            ah[1][0], ah[1][1], ah[1][2], ah[1][3], b0h, b1h);
                    mma_f16(t[0][nt][0], t[0][nt][1], t[0][nt][2], t[0][nt][3],
                            ah[0][0], ah[0][1], ah[0][2], ah[0][3], b0l, b1l);
                    mma_f16(t[1][nt][0], t[1][nt][1], t[1][nt][2], t[1][nt][3],
                            ah[1][0], ah[1][1], ah[1][2], ah[1][3], b0l, b1l);
                    mma_f16(t[0][nt][0], t[0][nt][1], t[0][nt][2], t[0][nt][3],
                            al[0][0], al[0][1], al[0][2], al[0][3], b0h, b1h);
                    mma_f16(t[1][nt][0], t[1][nt][1], t[1][nt][2], t[1][nt][3],
                            al[1][0], al[1][1], al[1][2], al[1][3], b0h, b1h);
                }
            }
        }

        // Fold t into hacc with exact fp32 x-scale
        float xv0 = xs[row0 * 68 + i];
        float xv1 = xs[(row0 + 8) * 68 + i];
        float xv2 = xs[(row0 + 16) * 68 + i];
        float xv3 = xs[(row0 + 24) * 68 + i];
#pragma unroll
        for (int nt = 0; nt < 8; nt++) {
            hacc[0][nt][0] += xv0 * t[0][nt][0];
            hacc[0][nt][1] += xv0 * t[0][nt][1];
            hacc[0][nt][2] += xv1 * t[0][nt][2];
            hacc[0][nt][3] += xv1 * t[0][nt][3];
            hacc[1][nt][0] += xv2 * t[1][nt][0];
            hacc[1][nt][1] += xv2 * t[1][nt][1];
            hacc[1][nt][2] += xv3 * t[1][nt][2];
            hacc[1][nt][3] += xv3 * t[1][nt][3];
        }
    }
}

// ---------------------------------------------------------------------------
// Fused kernel: 256 threads = 8 warps (4 wm x 2 wn), tile 128m x 128n,
// all 3 layers + d-reduction. SMEM:
//   [0..64)  mbar[3]
//   HsHi [64][136] u32 ; HsLo [64][136] u32   (sized for FI=128)
//   xs   [128][68] fp32
//   Bp   [3 slots][CH_U32] u32
__global__ __launch_bounds__(256, 1) void cin_fused(
    const float* __restrict__ xT,
    const uint32_t* __restrict__ w0,
    const uint32_t* __restrict__ w1,
    const uint32_t* __restrict__ w2,
    float* __restrict__ out) {
    extern __shared__ char smem[];
    constexpr int HB = 64;
    constexpr int HS_U32 = 64 * 136;               // max KP = 64
    constexpr int XB = HB + 2 * HS_U32 * 4;
    constexpr int BB = XB + 128 * 68 * 4;

    uint32_t* HsHi = reinterpret_cast<uint32_t*>(smem + HB);
    uint32_t* HsLo = HsHi + HS_U32;
    float* xs = reinterpret_cast<float*>(smem + XB);
    uint32_t* Bp = reinterpret_cast<uint32_t*>(smem + BB);
    const uint32_t sb = smem_u32(smem);
    const uint32_t bs_u32 = sb + BB;

    const int tid = threadIdx.x;
    const int lane = tid & 31;
    const int wid = tid >> 5;
    const int g = lane >> 2;     // 0..7
    const int c = lane & 3;      // 0..3
    const int wm = wid >> 1;     // 0..3
    const int wn = wid & 1;      // 0..1
    const int m0 = blockIdx.x * 128;
    const int row0 = wm * 32 + g;

    // Init mbars + prefetch chunks 0,1
    if (tid == 0) {
        mbar_init(sb + 0, 1);
        mbar_init(sb + 8, 1);
        mbar_init(sb + 16, 1);
    }
    __syncthreads();
    if (tid == 0) {
#pragma unroll
        for (int pc = 0; pc < 2; ++pc) {
            mbar_expect_tx(sb + pc * 8, CH_BYTES);
            bulk_g2s(bs_u32 + pc * CH_BYTES, chunk_src(w0, w1, w2, pc),
                     CH_BYTES, sb + pc * 8);
        }
    }

    // Layer-0 Hs from xT (FI=64 -> KP=32) + xs tile
    for (int idx = tid; idx < 128 * 32; idx += 256) {
        int p = idx & 31;
        int m = idx >> 5;
        float2 v = *reinterpret_cast<const float2*>(xT + (size_t)(m0 + m) * 64 + 2 * p);
        uint32_t hi, lo;
        pack_split(v.x, v.y, hi, lo);
        HsHi[p * 136 + m] = hi;
        HsLo[p * 136 + m] = lo;
    }
    {
        const float4* Xg = reinterpret_cast<const float4*>(xT + (size_t)m0 * 64);
        for (int idx = tid; idx < 128 * 16; idx += 256) {
            int m = idx >> 4;
            int seg = idx & 15;
            *reinterpret_cast<float4*>(xs + m * 68 + seg * 4) = Xg[idx];
        }
    }
    __syncthreads();

    int gch = 0;
    float hacc[2][8][4];

    for (int layer = 0; layer < 3; ++layer) {
#pragma unroll
        for (int mt = 0; mt < 2; mt++)
#pragma unroll
            for (int nt = 0; nt < 8; nt++)
#pragma unroll
                for (int q = 0; q < 4; q++) hacc[mt][nt][q] = 0.f;

        if (layer == 0)
            run_layer<2>(w0, w1, w2, sb, bs_u32, Bp, HsHi, HsLo, xs,
                         gch, tid, row0, c, wn, hacc);
        else
            run_layer<4>(w0, w1, w2, sb, bs_u32, Bp, HsHi, HsLo, xs,
                         gch, tid, row0, c, wn, hacc);

        // ---- out contribution: out[b, layer*128+n] = sum_d hacc rows ----
        // rows r=row0+mt*16 (d=g) and r+8 (d=g+8) belong to batch wm*2+mt.
#pragma unroll
        for (int mt = 0; mt < 2; mt++) {
            int b = (m0 >> 4) + wm * 2 + mt;
#pragma unroll
            for (int nt = 0; nt < 8; nt++) {
                float v0 = hacc[mt][nt][0] + hacc[mt][nt][2];
                float v1 = hacc[mt][nt][1] + hacc[mt][nt][3];
#pragma unroll
                for (int sh = 4; sh <= 16; sh <<= 1) {
                    v0 += __shfl_xor_sync(0xFFFFFFFFu, v0, sh);
                    v1 += __shfl_xor_sync(0xFFFFFFFFu, v1, sh);
                }
                if (g == 0) {
                    int col = wn * 64 + nt * 8 + 2 * c;
                    *reinterpret_cast<float2*>(out + (size_t)b * 384 + layer * 128 + col) =
                        make_float2(v0, v1);
                }
            }
        }

        // ---- rebuild Hs from hacc for next layer (FI=128 -> KP=64) ----
        if (layer < 2) {
            __syncthreads();   // everyone done reading old Hs
#pragma unroll
            for (int mt = 0; mt < 2; mt++) {
                int r = row0 + mt * 16;
#pragma unroll
                for (int nt = 0; nt < 8; nt++) {
                    int p = wn * 32 + nt * 4 + c;   // kpair = col/2
                    uint32_t hi, lo;
                    pack_split(hacc[mt][nt][0], hacc[mt][nt][1], hi, lo);
                    HsHi[p * 136 + r] = hi;
                    HsLo[p * 136 + r] = lo;
                    pack_split(hacc[mt][nt][2], hacc[mt][nt][3], hi, lo);
                    HsHi[p * 136 + r + 8] = hi;
                    HsLo[p * 136 + r + 8] = lo;
                }
            }
            __syncthreads();
        }
    }
}

// ---------------------------------------------------------------------------
extern "C" void kernel_launch(void* const* d_in, const int* in_sizes, int n_in,
                              void* d_out, int out_size) {
    const float* x  = (const float*)d_in[0];
    const float* W0 = (const float*)d_in[1];
    const float* W1 = (const float*)d_in[2];
    const float* W2 = (const float*)d_in[3];
    float* out = (float*)d_out;

    float* xT;
    uint32_t* wp;
    cudaGetSymbolAddress((void**)&xT, g_xT);
    cudaGetSymbolAddress((void**)&wp, g_wp);

    uint32_t* wp_0 = wp;
    uint32_t* wp_1 = wp + (size_t)128 * CH_U32;
    uint32_t* wp_2 = wp_1 + (size_t)256 * CH_U32;

    // SMEM (bytes): 64 + 2*Hs(64x136 u32) + xs + 3 B slots = 156,736
    const int smemF = 64 + (2 * 64 * 136 + 128 * 68) * 4 + 3 * CH_BYTES;
    cudaFuncSetAttribute(cin_fused, cudaFuncAttributeMaxDynamicSharedMemorySize, smemF);

    // Prep
    k_xT<<<(CIN_M * CIN_F0 + 255) / 256, 256>>>(x, xT);
    k_wp<<<2048, 256>>>(W0, wp_0, 64);
    k_wp<<<2048, 256>>>(W1, wp_1, 128);
    k_wp<<<2048, 256>>>(W2, wp_2, 128);

    // Fused 3-layer GEMM + reduction (grid = 256 tiles)
    cin_fused<<<CIN_M / 128, 256, smemF>>>(xT, wp_0, wp_1, wp_2, out);
}

// round 13
// speedup vs baseline: 1.2030x; 1.0623x over previous
#include <cuda_runtime.h>
#include <cuda_fp16.h>
#include <cstdint>

// ============================================================================
// CIN fully fused (3 layers + d-reduce in ONE kernel), mma.sync m16n8k16 FP16,
// 3-term hi/lo split, x-scale folded in fp32 per i.
// R13: 64-K chunks (34816 B) -- halves per-chunk fixed costs (mbar_wait, BAR,
// bulk issue): 320 chunks instead of 640. Ring of 3 slots, SMEM 208.9 KB.
// ============================================================================

#define CIN_B   2048
#define CIN_F0  64
#define CIN_D   16
#define CIN_FN  128
#define CIN_M   (CIN_B * CIN_D)   // 32768

// Per 64-K chunk: [hi 32 kpairs x 136 u32][lo 32 x 136] = 8704 u32 = 34816 B
#define CH_U32  8704
#define CH_HALF 4352
#define CH_BYTES 34816u
#define TOTAL_CHUNKS 320          // 64 (l0) + 128 (l1) + 128 (l2)

// Device scratch
__device__ float    g_xT[CIN_M * CIN_F0];                    // 8 MB
__device__ uint32_t g_wp[(64 + 128 + 128) * CH_U32];         // 11.1 MB fp16 pairs

// ---------------------------------------------------------------------------
__device__ __forceinline__ uint32_t smem_u32(const void* p) {
    uint32_t a;
    asm("{ .reg .u64 t; cvta.to.shared.u64 t, %1; cvt.u32.u64 %0, t; }" : "=r"(a) : "l"(p));
    return a;
}
__device__ __forceinline__ void mbar_init(uint32_t mbar, uint32_t cnt) {
    asm volatile("mbarrier.init.shared.b64 [%0], %1;" :: "r"(mbar), "r"(cnt) : "memory");
}
__device__ __forceinline__ void mbar_expect_tx(uint32_t mbar, uint32_t bytes) {
    asm volatile("mbarrier.arrive.expect_tx.shared.b64 _, [%0], %1;"
                 :: "r"(mbar), "r"(bytes) : "memory");
}
__device__ __forceinline__ void mbar_wait(uint32_t mbar, uint32_t parity) {
    uint32_t done = 0;
    while (!done) {
        asm volatile(
            "{\n\t.reg .pred p;\n\t"
            "mbarrier.try_wait.parity.shared.b64 p, [%1], %2;\n\t"
            "selp.b32 %0, 1, 0, p;\n\t}"
            : "=r"(done) : "r"(mbar), "r"(parity) : "memory");
    }
}
__device__ __forceinline__ void bulk_g2s(uint32_t dst, const void* src, uint32_t bytes,
                                         uint32_t mbar) {
    asm volatile(
        "cp.async.bulk.shared::cluster.global.mbarrier::complete_tx::bytes "
        "[%0], [%1], %2, [%3];"
        :: "r"(dst), "l"(src), "r"(bytes), "r"(mbar) : "memory");
}
__device__ __forceinline__ void mma_f16(float& d0, float& d1, float& d2, float& d3,
                                        uint32_t a0, uint32_t a1, uint32_t a2, uint32_t a3,
                                        uint32_t b0, uint32_t b1) {
    asm volatile(
        "mma.sync.aligned.m16n8k16.row.col.f32.f16.f16.f32 "
        "{%0,%1,%2,%3}, {%4,%5,%6,%7}, {%8,%9}, {%0,%1,%2,%3};"
        : "+f"(d0), "+f"(d1), "+f"(d2), "+f"(d3)
        : "r"(a0), "r"(a1), "r"(a2), "r"(a3), "r"(b0), "r"(b1));
}
__device__ __forceinline__ void pack_split(float v0, float v1, uint32_t& hi, uint32_t& lo) {
    __half2 h = __floats2half2_rn(v0, v1);
    float2 back = __half22float2(h);
    __half2 l = __floats2half2_rn(v0 - back.x, v1 - back.y);
    hi = *reinterpret_cast<uint32_t*>(&h);
    lo = *reinterpret_cast<uint32_t*>(&l);
}
__device__ __forceinline__ const uint32_t* chunk_src(
    const uint32_t* w0, const uint32_t* w1, const uint32_t* w2, int gch) {
    if (gch < 64) return w0 + (size_t)gch * CH_U32;
    if (gch < 192) return w1 + (size_t)(gch - 64) * CH_U32;
    return w2 + (size_t)(gch - 192) * CH_U32;
}

// ---------------------------------------------------------------------------
// Prep: x [B, F0, D] -> xT [(b*16+d), 64]
__global__ void k_xT(const float* __restrict__ x, float* __restrict__ xT) {
    int o = blockIdx.x * 256 + threadIdx.x;
    if (o >= CIN_M * CIN_F0) return;
    int i = o & 63;
    int m = o >> 6;
    int b = m >> 4;
    int d = m & 15;
    xT[o] = x[(b * CIN_F0 + i) * CIN_D + d];
}

// Prep: W -> fp16 hi/lo pairs per 64-K chunk.
// chunk s = i*(Fi/64)+jc; kpair p (0..31) covers j = jc*64 + 2p, 2p+1.
__global__ void k_wp(const float* __restrict__ W, uint32_t* __restrict__ dst, int Fi) {
    int CPI = Fi >> 6;                 // chunks per i (1 or 2)
    int total = (CIN_F0 * CPI) * 32 * 128;
    for (int o = blockIdx.x * 256 + threadIdx.x; o < total; o += gridDim.x * 256) {
        int n = o & 127;
        int p = (o >> 7) & 31;
        int s = o >> 12;               // 4096 items per chunk
        int i = s / CPI;
        int jc = s - i * CPI;
        int j0 = jc * 64 + 2 * p;
        float v0 = W[(i * Fi + j0) * 128 + n];
        float v1 = W[(i * Fi + j0 + 1) * 128 + n];
        uint32_t hi, lo;
        pack_split(v0, v1, hi, lo);
        uint32_t base = (uint32_t)s * CH_U32 + p * 136 + n;
        dst[base] = hi;
        dst[base + CH_HALF] = lo;
    }
}

// ---------------------------------------------------------------------------
// One layer's mainloop. CPI = FI/64 chunks per i (1 for FI=64, 2 for FI=128).
template <int CPI>
__device__ __forceinline__ void run_layer(
    const uint32_t* __restrict__ w0, const uint32_t* __restrict__ w1,
    const uint32_t* __restrict__ w2,
    uint32_t sb, uint32_t bs_u32, const uint32_t* __restrict__ Bp,
    const uint32_t* __restrict__ HsHi, const uint32_t* __restrict__ HsLo,
    const float* __restrict__ xs,
    int& gch, int tid, int row0, int g, int c, int wn,
    float hacc[2][8][4]) {
    for (int i = 0; i < CIN_F0; ++i) {
        float t[2][8][4];
#pragma unroll
        for (int mt = 0; mt < 2; mt++)
#pragma unroll
            for (int nt = 0; nt < 8; nt++)
#pragma unroll
                for (int q = 0; q < 4; q++) t[mt][nt][q] = 0.f;

#pragma unroll
        for (int jc = 0; jc < CPI; ++jc, ++gch) {
            const int slot = gch % 3;
            mbar_wait(sb + slot * 8, (gch / 3) & 1);
            __syncthreads();
            if (tid == 0 && gch + 2 < TOTAL_CHUNKS) {
                const int ns = (gch + 2) % 3;
                mbar_expect_tx(sb + ns * 8, CH_BYTES);
                bulk_g2s(bs_u32 + ns * CH_BYTES, chunk_src(w0, w1, w2, gch + 2),
                         CH_BYTES, sb + ns * 8);
            }

            const uint32_t* Bc = Bp + slot * CH_U32;
#pragma unroll
            for (int ks = 0; ks < 4; ++ks) {
                const int kp0 = jc * 32 + ks * 8 + c;
                uint32_t ah[2][4], al[2][4];
#pragma unroll
                for (int mt = 0; mt < 2; mt++) {
                    int r = row0 + mt * 16;
                    ah[mt][0] = HsHi[kp0 * 136 + r];
                    ah[mt][1] = HsHi[kp0 * 136 + r + 8];
                    ah[mt][2] = HsHi[(kp0 + 4) * 136 + r];
                    ah[mt][3] = HsHi[(kp0 + 4) * 136 + r + 8];
                    al[mt][0] = HsLo[kp0 * 136 + r];
                    al[mt][1] = HsLo[kp0 * 136 + r + 8];
                    al[mt][2] = HsLo[(kp0 + 4) * 136 + r];
                    al[mt][3] = HsLo[(kp0 + 4) * 136 + r + 8];
                }
                const int p0 = (ks * 8 + c) * 136;
                const int p1 = p0 + 4 * 136;
#pragma unroll
                for (int nt = 0; nt < 8; ++nt) {
                    int ncol = wn * 64 + nt * 8 + g;
                    uint32_t b0h = Bc[p0 + ncol];
                    uint32_t b1h = Bc[p1 + ncol];
                    uint32_t b0l = Bc[CH_HALF + p0 + ncol];
                    uint32_t b1l = Bc[CH_HALF + p1 + ncol];
                    mma_f16(t[0][nt][0], t[0][nt][1], t[0][nt][2], t[0][nt][3],
                            ah[0][0], ah[0][1], ah[0][2], ah[0][3], b0h, b1h);
                    mma_f16(t[1][nt][0], t[1][nt][1], t[1][nt][2], t[1][nt][3],
                            ah[1][0], ah[1][1], ah[1][2], ah[1][3], b0h, b1h);
                    mma_f16(t[0][nt][0], t[0][nt][1], t[0][nt][2], t[0][nt][3],
                            ah[0][0], ah[0][1], ah[0][2], ah[0][3], b0l, b1l);
                    mma_f16(t[1][nt][0], t[1][nt][1], t[1][nt][2], t[1][nt][3],
                            ah[1][0], ah[1][1], ah[1][2], ah[1][3], b0l, b1l);
                    mma_f16(t[0][nt][0], t[0][nt][1], t[0][nt][2], t[0][nt][3],
                            al[0][0], al[0][1], al[0][2], al[0][3], b0h, b1h);
                    mma_f16(t[1][nt][0], t[1][nt][1], t[1][nt][2], t[1][nt][3],
                            al[1][0], al[1][1], al[1][2], al[1][3], b0h, b1h);
                }
            }
        }

        // Fold t into hacc with exact fp32 x-scale
        float xv0 = xs[row0 * 68 + i];
        float xv1 = xs[(row0 + 8) * 68 + i];
        float xv2 = xs[(row0 + 16) * 68 + i];
        float xv3 = xs[(row0 + 24) * 68 + i];
#pragma unroll
        for (int nt = 0; nt < 8; nt++) {
            hacc[0][nt][0] += xv0 * t[0][nt][0];
            hacc[0][nt][1] += xv0 * t[0][nt][1];
            hacc[0][nt][2] += xv1 * t[0][nt][2];
            hacc[0][nt][3] += xv1 * t[0][nt][3];
            hacc[1][nt][0] += xv2 * t[1][nt][0];
            hacc[1][nt][1] += xv2 * t[1][nt][1];
            hacc[1][nt][2] += xv3 * t[1][nt][2];
            hacc[1][nt][3] += xv3 * t[1][nt][3];
        }
    }
}

// ---------------------------------------------------------------------------
// Fused kernel: 256 threads = 8 warps (4 wm x 2 wn), tile 128m x 128n.
// SMEM: [0..64) mbar[3] | HsHi[64][136] HsLo[64][136] | xs[128][68] | 3 B slots
__global__ __launch_bounds__(256, 1) void cin_fused(
    const float* __restrict__ xT,
    const uint32_t* __restrict__ w0,
    const uint32_t* __restrict__ w1,
    const uint32_t* __restrict__ w2,
    float* __restrict__ out) {
    extern __shared__ char smem[];
    constexpr int HB = 64;
    constexpr int HS_U32 = 64 * 136;
    constexpr int XB = HB + 2 * HS_U32 * 4;
    constexpr int BB = XB + 128 * 68 * 4;

    uint32_t* HsHi = reinterpret_cast<uint32_t*>(smem + HB);
    uint32_t* HsLo = HsHi + HS_U32;
    float* xs = reinterpret_cast<float*>(smem + XB);
    uint32_t* Bp = reinterpret_cast<uint32_t*>(smem + BB);
    const uint32_t sb = smem_u32(smem);
    const uint32_t bs_u32 = sb + BB;

    const int tid = threadIdx.x;
    const int lane = tid & 31;
    const int wid = tid >> 5;
    const int g = lane >> 2;
    const int c = lane & 3;
    const int wm = wid >> 1;
    const int wn = wid & 1;
    const int m0 = blockIdx.x * 128;
    const int row0 = wm * 32 + g;

    if (tid == 0) {
        mbar_init(sb + 0, 1);
        mbar_init(sb + 8, 1);
        mbar_init(sb + 16, 1);
    }
    __syncthreads();
    if (tid == 0) {
#pragma unroll
        for (int pc = 0; pc < 2; ++pc) {
            mbar_expect_tx(sb + pc * 8, CH_BYTES);
            bulk_g2s(bs_u32 + pc * CH_BYTES, chunk_src(w0, w1, w2, pc),
                     CH_BYTES, sb + pc * 8);
        }
    }

    // Layer-0 Hs from xT (KP=32) + xs tile
    for (int idx = tid; idx < 128 * 32; idx += 256) {
        int p = idx & 31;
        int m = idx >> 5;
        float2 v = *reinterpret_cast<const float2*>(xT + (size_t)(m0 + m) * 64 + 2 * p);
        uint32_t hi, lo;
        pack_split(v.x, v.y, hi, lo);
        HsHi[p * 136 + m] = hi;
        HsLo[p * 136 + m] = lo;
    }
    {
        const float4* Xg = reinterpret_cast<const float4*>(xT + (size_t)m0 * 64);
        for (int idx = tid; idx < 128 * 16; idx += 256) {
            int m = idx >> 4;
            int seg = idx & 15;
            *reinterpret_cast<float4*>(xs + m * 68 + seg * 4) = Xg[idx];
        }
    }
    __syncthreads();

    int gch = 0;
    float hacc[2][8][4];

    for (int layer = 0; layer < 3; ++layer) {
#pragma unroll
        for (int mt = 0; mt < 2; mt++)
#pragma unroll
            for (int nt = 0; nt < 8; nt++)
#pragma unroll
                for (int q = 0; q < 4; q++) hacc[mt][nt][q] = 0.f;

        if (layer == 0)
            run_layer<1>(w0, w1, w2, sb, bs_u32, Bp, HsHi, HsLo, xs,
                         gch, tid, row0, g, c, wn, hacc);
        else
            run_layer<2>(w0, w1, w2, sb, bs_u32, Bp, HsHi, HsLo, xs,
                         gch, tid, row0, g, c, wn, hacc);

        // out[b, layer*128+n] = sum_d over rows (d = g / g+8 within batch)
#pragma unroll
        for (int mt = 0; mt < 2; mt++) {
            int b = (m0 >> 4) + wm * 2 + mt;
#pragma unroll
            for (int nt = 0; nt < 8; nt++) {
                float v0 = hacc[mt][nt][0] + hacc[mt][nt][2];
                float v1 = hacc[mt][nt][1] + hacc[mt][nt][3];
#pragma unroll
                for (int sh = 4; sh <= 16; sh <<= 1) {
                    v0 += __shfl_xor_sync(0xFFFFFFFFu, v0, sh);
                    v1 += __shfl_xor_sync(0xFFFFFFFFu, v1, sh);
                }
                if (g == 0) {
                    int col = wn * 64 + nt * 8 + 2 * c;
                    *reinterpret_cast<float2*>(out + (size_t)b * 384 + layer * 128 + col) =
                        make_float2(v0, v1);
                }
            }
        }

        // Rebuild Hs from hacc for next layer (KP=64)
        if (layer < 2) {
            __syncthreads();
#pragma unroll
            for (int mt = 0; mt < 2; mt++) {
                int r = row0 + mt * 16;
#pragma unroll
                for (int nt = 0; nt < 8; nt++) {
                    int p = wn * 32 + nt * 4 + c;
                    uint32_t hi, lo;
                    pack_split(hacc[mt][nt][0], hacc[mt][nt][1], hi, lo);
                    HsHi[p * 136 + r] = hi;
                    HsLo[p * 136 + r] = lo;
                    pack_split(hacc[mt][nt][2], hacc[mt][nt][3], hi, lo);
                    HsHi[p * 136 + r + 8] = hi;
                    HsLo[p * 136 + r + 8] = lo;
                }
            }
            __syncthreads();
        }
    }
}

// ---------------------------------------------------------------------------
extern "C" void kernel_launch(void* const* d_in, const int* in_sizes, int n_in,
                              void* d_out, int out_size) {
    const float* x  = (const float*)d_in[0];
    const float* W0 = (const float*)d_in[1];
    const float* W1 = (const float*)d_in[2];
    const float* W2 = (const float*)d_in[3];
    float* out = (float*)d_out;

    float* xT;
    uint32_t* wp;
    cudaGetSymbolAddress((void**)&xT, g_xT);
    cudaGetSymbolAddress((void**)&wp, g_wp);

    uint32_t* wp_0 = wp;                          // 64 chunks
    uint32_t* wp_1 = wp + (size_t)64 * CH_U32;    // 128 chunks
    uint32_t* wp_2 = wp_1 + (size_t)128 * CH_U32; // 128 chunks

    // SMEM: 64 + 69632 (Hs) + 34816 (xs) + 104448 (3 slots) = 208,960 B
    const int smemF = 64 + (2 * 64 * 136 + 128 * 68) * 4 + 3 * CH_BYTES;
    cudaFuncSetAttribute(cin_fused, cudaFuncAttributeMaxDynamicSharedMemorySize, smemF);

    // Prep
    k_xT<<<(CIN_M * CIN_F0 + 255) / 256, 256>>>(x, xT);
    k_wp<<<2048, 256>>>(W0, wp_0, 64);
    k_wp<<<2048, 256>>>(W1, wp_1, 128);
    k_wp<<<2048, 256>>>(W2, wp_2, 128);

    // Fused 3-layer GEMM + reduction (grid = 256 tiles)
    cin_fused<<<CIN_M / 128, 256, smemF>>>(xT, wp_0, wp_1, wp_2, out);
}

// round 14
// speedup vs baseline: 1.7761x; 1.4764x over previous
#include <cuda_runtime.h>
#include <cuda_fp16.h>
#include <cstdint>

// ============================================================================
// CIN fully fused (3 layers + d-reduce, ONE kernel), mma.sync m16n8k16 FP16.
// R14: 2-term split  a*b ~= (ah+al)*bh  -- A keeps hi/lo split (2 MMAs),
// W stored as plain fp16 (B-lo dropped; error ~2^-12 from W quantization,
// budgeted against the 500x rel_err margin). B bytes halve -> 128-K chunks
// (34816 B), 160 total chunks, halving per-chunk fixed costs again.
// ============================================================================

#define CIN_B   2048
#define CIN_F0  64
#define CIN_D   16
#define CIN_FN  128
#define CIN_M   (CIN_B * CIN_D)   // 32768

// Per 128-K chunk (hi only): 64 kpairs x 136 u32 = 8704 u32 = 34816 B
#define CH_U32  8704
#define CH_BYTES 34816u
#define TOTAL_CHUNKS 160          // 32 (l0) + 64 (l1) + 64 (l2)

// Device scratch
__device__ float    g_xT[CIN_M * CIN_F0];                    // 8 MB
__device__ uint32_t g_wp[(32 + 64 + 64) * CH_U32];           // 5.6 MB fp16 pairs

// ---------------------------------------------------------------------------
__device__ __forceinline__ uint32_t smem_u32(const void* p) {
    uint32_t a;
    asm("{ .reg .u64 t; cvta.to.shared.u64 t, %1; cvt.u32.u64 %0, t; }" : "=r"(a) : "l"(p));
    return a;
}
__device__ __forceinline__ void mbar_init(uint32_t mbar, uint32_t cnt) {
    asm volatile("mbarrier.init.shared.b64 [%0], %1;" :: "r"(mbar), "r"(cnt) : "memory");
}
__device__ __forceinline__ void mbar_expect_tx(uint32_t mbar, uint32_t bytes) {
    asm volatile("mbarrier.arrive.expect_tx.shared.b64 _, [%0], %1;"
                 :: "r"(mbar), "r"(bytes) : "memory");
}
__device__ __forceinline__ void mbar_wait(uint32_t mbar, uint32_t parity) {
    uint32_t done = 0;
    while (!done) {
        asm volatile(
            "{\n\t.reg .pred p;\n\t"
            "mbarrier.try_wait.parity.shared.b64 p, [%1], %2;\n\t"
            "selp.b32 %0, 1, 0, p;\n\t}"
            : "=r"(done) : "r"(mbar), "r"(parity) : "memory");
    }
}
__device__ __forceinline__ void bulk_g2s(uint32_t dst, const void* src, uint32_t bytes,
                                         uint32_t mbar) {
    asm volatile(
        "cp.async.bulk.shared::cluster.global.mbarrier::complete_tx::bytes "
        "[%0], [%1], %2, [%3];"
        :: "r"(dst), "l"(src), "r"(bytes), "r"(mbar) : "memory");
}
__device__ __forceinline__ void mma_f16(float& d0, float& d1, float& d2, float& d3,
                                        uint32_t a0, uint32_t a1, uint32_t a2, uint32_t a3,
                                        uint32_t b0, uint32_t b1) {
    asm volatile(
        "mma.sync.aligned.m16n8k16.row.col.f32.f16.f16.f32 "
        "{%0,%1,%2,%3}, {%4,%5,%6,%7}, {%8,%9}, {%0,%1,%2,%3};"
        : "+f"(d0), "+f"(d1), "+f"(d2), "+f"(d3)
        : "r"(a0), "r"(a1), "r"(a2), "r"(a3), "r"(b0), "r"(b1));
}
__device__ __forceinline__ void pack_split(float v0, float v1, uint32_t& hi, uint32_t& lo) {
    __half2 h = __floats2half2_rn(v0, v1);
    float2 back = __half22float2(h);
    __half2 l = __floats2half2_rn(v0 - back.x, v1 - back.y);
    hi = *reinterpret_cast<uint32_t*>(&h);
    lo = *reinterpret_cast<uint32_t*>(&l);
}
__device__ __forceinline__ uint32_t pack_hi(float v0, float v1) {
    __half2 h = __floats2half2_rn(v0, v1);
    return *reinterpret_cast<uint32_t*>(&h);
}
__device__ __forceinline__ const uint32_t* chunk_src(
    const uint32_t* w0, const uint32_t* w1, const uint32_t* w2, int gch) {
    if (gch < 32) return w0 + (size_t)gch * CH_U32;
    if (gch < 96) return w1 + (size_t)(gch - 32) * CH_U32;
    return w2 + (size_t)(gch - 96) * CH_U32;
}

// ---------------------------------------------------------------------------
// Prep: x [B, F0, D] -> xT [(b*16+d), 64]
__global__ void k_xT(const float* __restrict__ x, float* __restrict__ xT) {
    int o = blockIdx.x * 256 + threadIdx.x;
    if (o >= CIN_M * CIN_F0) return;
    int i = o & 63;
    int m = o >> 6;
    int b = m >> 4;
    int d = m & 15;
    xT[o] = x[(b * CIN_F0 + i) * CIN_D + d];
}

// Prep: W [F0*Fi, 128] -> fp16 (hi only) in 128-K' chunks.
// Global kpair gp = s*64 + p covers K' = 2*gp, 2*gp+1 where K' = i*Fi + j.
__global__ void k_wp(const float* __restrict__ W, uint32_t* __restrict__ dst, int Fi) {
    int total = CIN_F0 * Fi * 128 / 2;   // one half2 per item
    for (int o = blockIdx.x * 256 + threadIdx.x; o < total; o += gridDim.x * 256) {
        int n = o & 127;
        int gp = o >> 7;                 // global kpair
        int s = gp >> 6;
        int p = gp & 63;
        int k0 = gp * 2;                 // = i*Fi + j
        float v0 = W[(size_t)k0 * 128 + n];
        float v1 = W[(size_t)(k0 + 1) * 128 + n];
        dst[(size_t)s * CH_U32 + p * 136 + n] = pack_hi(v0, v1);
    }
}

// ---------------------------------------------------------------------------
// MMA micro-step: one k16 group. A kpairs from Hs at akp0/akp0+4; B rows at
// chunk kpairs bkp0/bkp0+4. 2-term: ah*bh + al*bh, mt-interleaved.
__device__ __forceinline__ void mma_group(
    const uint32_t* __restrict__ HsHi, const uint32_t* __restrict__ HsLo,
    const uint32_t* __restrict__ Bc, int akp0, int bkp0,
    int row0, int g, int wn, float t[2][8][4]) {
    uint32_t ah[2][4], al[2][4];
#pragma unroll
    for (int mt = 0; mt < 2; mt++) {
        int r = row0 + mt * 16;
        ah[mt][0] = HsHi[akp0 * 136 + r];
        ah[mt][1] = HsHi[akp0 * 136 + r + 8];
        ah[mt][2] = HsHi[(akp0 + 4) * 136 + r];
        ah[mt][3] = HsHi[(akp0 + 4) * 136 + r + 8];
        al[mt][0] = HsLo[akp0 * 136 + r];
        al[mt][1] = HsLo[akp0 * 136 + r + 8];
        al[mt][2] = HsLo[(akp0 + 4) * 136 + r];
        al[mt][3] = HsLo[(akp0 + 4) * 136 + r + 8];
    }
    const int p0 = bkp0 * 136;
    const int p1 = p0 + 4 * 136;
#pragma unroll
    for (int nt = 0; nt < 8; ++nt) {
        int ncol = wn * 64 + nt * 8 + g;
        uint32_t b0 = Bc[p0 + ncol];
        uint32_t b1 = Bc[p1 + ncol];
        mma_f16(t[0][nt][0], t[0][nt][1], t[0][nt][2], t[0][nt][3],
                ah[0][0], ah[0][1], ah[0][2], ah[0][3], b0, b1);
        mma_f16(t[1][nt][0], t[1][nt][1], t[1][nt][2], t[1][nt][3],
                ah[1][0], ah[1][1], ah[1][2], ah[1][3], b0, b1);
        mma_f16(t[0][nt][0], t[0][nt][1], t[0][nt][2], t[0][nt][3],
                al[0][0], al[0][1], al[0][2], al[0][3], b0, b1);
        mma_f16(t[1][nt][0], t[1][nt][1], t[1][nt][2], t[1][nt][3],
                al[1][0], al[1][1], al[1][2], al[1][3], b0, b1);
    }
}

__device__ __forceinline__ void zero_t(float t[2][8][4]) {
#pragma unroll
    for (int mt = 0; mt < 2; mt++)
#pragma unroll
        for (int nt = 0; nt < 8; nt++)
#pragma unroll
            for (int q = 0; q < 4; q++) t[mt][nt][q] = 0.f;
}

__device__ __forceinline__ void fold_t(
    const float* __restrict__ xs, int i, int row0,
    float t[2][8][4], float hacc[2][8][4]) {
    float xv0 = xs[row0 * 68 + i];
    float xv1 = xs[(row0 + 8) * 68 + i];
    float xv2 = xs[(row0 + 16) * 68 + i];
    float xv3 = xs[(row0 + 24) * 68 + i];
#pragma unroll
    for (int nt = 0; nt < 8; nt++) {
        hacc[0][nt][0] += xv0 * t[0][nt][0];
        hacc[0][nt][1] += xv0 * t[0][nt][1];
        hacc[0][nt][2] += xv1 * t[0][nt][2];
        hacc[0][nt][3] += xv1 * t[0][nt][3];
        hacc[1][nt][0] += xv2 * t[1][nt][0];
        hacc[1][nt][1] += xv2 * t[1][nt][1];
        hacc[1][nt][2] += xv3 * t[1][nt][2];
        hacc[1][nt][3] += xv3 * t[1][nt][3];
    }
}

// Ring step: wait chunk gch, barrier, prefetch gch+2. Returns slot base.
__device__ __forceinline__ const uint32_t* ring_step(
    const uint32_t* __restrict__ w0, const uint32_t* __restrict__ w1,
    const uint32_t* __restrict__ w2,
    uint32_t sb, uint32_t bs_u32, const uint32_t* __restrict__ Bp,
    int gch, int tid) {
    const int slot = gch % 3;
    mbar_wait(sb + slot * 8, (gch / 3) & 1);
    __syncthreads();
    if (tid == 0 && gch + 2 < TOTAL_CHUNKS) {
        const int ns = (gch + 2) % 3;
        mbar_expect_tx(sb + ns * 8, CH_BYTES);
        bulk_g2s(bs_u32 + ns * CH_BYTES, chunk_src(w0, w1, w2, gch + 2),
                 CH_BYTES, sb + ns * 8);
    }
    return Bp + slot * CH_U32;
}

// ---------------------------------------------------------------------------
// Fused kernel: 256 threads = 8 warps (4 wm x 2 wn), tile 128m x 128n.
// SMEM: [0..64) mbar[3] | HsHi[64][136] HsLo[64][136] | xs[128][68] | 3 B slots
__global__ __launch_bounds__(256, 1) void cin_fused(
    const float* __restrict__ xT,
    const uint32_t* __restrict__ w0,
    const uint32_t* __restrict__ w1,
    const uint32_t* __restrict__ w2,
    float* __restrict__ out) {
    extern __shared__ char smem[];
    constexpr int HB = 64;
    constexpr int HS_U32 = 64 * 136;
    constexpr int XB = HB + 2 * HS_U32 * 4;
    constexpr int BB = XB + 128 * 68 * 4;

    uint32_t* HsHi = reinterpret_cast<uint32_t*>(smem + HB);
    uint32_t* HsLo = HsHi + HS_U32;
    float* xs = reinterpret_cast<float*>(smem + XB);
    uint32_t* Bp = reinterpret_cast<uint32_t*>(smem + BB);
    const uint32_t sb = smem_u32(smem);
    const uint32_t bs_u32 = sb + BB;

    const int tid = threadIdx.x;
    const int lane = tid & 31;
    const int wid = tid >> 5;
    const int g = lane >> 2;
    const int c = lane & 3;
    const int wm = wid >> 1;
    const int wn = wid & 1;
    const int m0 = blockIdx.x * 128;
    const int row0 = wm * 32 + g;

    if (tid == 0) {
        mbar_init(sb + 0, 1);
        mbar_init(sb + 8, 1);
        mbar_init(sb + 16, 1);
    }
    __syncthreads();
    if (tid == 0) {
#pragma unroll
        for (int pc = 0; pc < 2; ++pc) {
            mbar_expect_tx(sb + pc * 8, CH_BYTES);
            bulk_g2s(bs_u32 + pc * CH_BYTES, chunk_src(w0, w1, w2, pc),
                     CH_BYTES, sb + pc * 8);
        }
    }

    // Layer-0 Hs from xT (KP=32) + xs tile
    for (int idx = tid; idx < 128 * 32; idx += 256) {
        int p = idx & 31;
        int m = idx >> 5;
        float2 v = *reinterpret_cast<const float2*>(xT + (size_t)(m0 + m) * 64 + 2 * p);
        uint32_t hi, lo;
        pack_split(v.x, v.y, hi, lo);
        HsHi[p * 136 + m] = hi;
        HsLo[p * 136 + m] = lo;
    }
    {
        const float4* Xg = reinterpret_cast<const float4*>(xT + (size_t)m0 * 64);
        for (int idx = tid; idx < 128 * 16; idx += 256) {
            int m = idx >> 4;
            int seg = idx & 15;
            *reinterpret_cast<float4*>(xs + m * 68 + seg * 4) = Xg[idx];
        }
    }
    __syncthreads();

    float hacc[2][8][4];
    float t[2][8][4];
    int gch = 0;

    for (int layer = 0; layer < 3; ++layer) {
#pragma unroll
        for (int mt = 0; mt < 2; mt++)
#pragma unroll
            for (int nt = 0; nt < 8; nt++)
#pragma unroll
                for (int q = 0; q < 4; q++) hacc[mt][nt][q] = 0.f;

        if (layer == 0) {
            // FI=64: each 128-K chunk covers TWO i values (halves of 64 K each)
            for (int s = 0; s < 32; ++s, ++gch) {
                const uint32_t* Bc = ring_step(w0, w1, w2, sb, bs_u32, Bp, gch, tid);
#pragma unroll
                for (int half = 0; half < 2; ++half) {
                    zero_t(t);
#pragma unroll
                    for (int ks = 0; ks < 4; ++ks) {
                        int akp0 = ks * 8 + c;              // Hs kpair (KP=32)
                        int bkp0 = half * 32 + ks * 8 + c;  // chunk kpair
                        mma_group(HsHi, HsLo, Bc, akp0, bkp0, row0, g, wn, t);
                    }
                    fold_t(xs, 2 * s + half, row0, t, hacc);
                }
            }
        } else {
            // FI=128: one chunk per i
            for (int s = 0; s < 64; ++s, ++gch) {
                const uint32_t* Bc = ring_step(w0, w1, w2, sb, bs_u32, Bp, gch, tid);
                zero_t(t);
#pragma unroll
                for (int ks = 0; ks < 8; ++ks) {
                    int kp0 = ks * 8 + c;
                    mma_group(HsHi, HsLo, Bc, kp0, kp0, row0, g, wn, t);
                }
                fold_t(xs, s, row0, t, hacc);
            }
        }

        // out[b, layer*128+n] = sum_d
#pragma unroll
        for (int mt = 0; mt < 2; mt++) {
            int b = (m0 >> 4) + wm * 2 + mt;
#pragma unroll
            for (int nt = 0; nt < 8; nt++) {
                float v0 = hacc[mt][nt][0] + hacc[mt][nt][2];
                float v1 = hacc[mt][nt][1] + hacc[mt][nt][3];
#pragma unroll
                for (int sh = 4; sh <= 16; sh <<= 1) {
                    v0 += __shfl_xor_sync(0xFFFFFFFFu, v0, sh);
                    v1 += __shfl_xor_sync(0xFFFFFFFFu, v1, sh);
                }
                if (g == 0) {
                    int col = wn * 64 + nt * 8 + 2 * c;
                    *reinterpret_cast<float2*>(out + (size_t)b * 384 + layer * 128 + col) =
                        make_float2(v0, v1);
                }
            }
        }

        // Rebuild Hs from hacc for next layer (KP=64)
        if (layer < 2) {
            __syncthreads();
#pragma unroll
            for (int mt = 0; mt < 2; mt++) {
                int r = row0 + mt * 16;
#pragma unroll
                for (int nt = 0; nt < 8; nt++) {
                    int p = wn * 32 + nt * 4 + c;
                    uint32_t hi, lo;
                    pack_split(hacc[mt][nt][0], hacc[mt][nt][1], hi, lo);
                    HsHi[p * 136 + r] = hi;
                    HsLo[p * 136 + r] = lo;
                    pack_split(hacc[mt][nt][2], hacc[mt][nt][3], hi, lo);
                    HsHi[p * 136 + r + 8] = hi;
                    HsLo[p * 136 + r + 8] = lo;
                }
            }
            __syncthreads();
        }
    }
}

// ---------------------------------------------------------------------------
extern "C" void kernel_launch(void* const* d_in, const int* in_sizes, int n_in,
                              void* d_out, int out_size) {
    const float* x  = (const float*)d_in[0];
    const float* W0 = (const float*)d_in[1];
    const float* W1 = (const float*)d_in[2];
    const float* W2 = (const float*)d_in[3];
    float* out = (float*)d_out;

    float* xT;
    uint32_t* wp;
    cudaGetSymbolAddress((void**)&xT, g_xT);
    cudaGetSymbolAddress((void**)&wp, g_wp);

    uint32_t* wp_0 = wp;                          // 32 chunks
    uint32_t* wp_1 = wp + (size_t)32 * CH_U32;    // 64 chunks
    uint32_t* wp_2 = wp_1 + (size_t)64 * CH_U32;  // 64 chunks

    // SMEM: 64 + 69632 (Hs) + 34816 (xs) + 104448 (3 slots) = 208,960 B
    const int smemF = 64 + (2 * 64 * 136 + 128 * 68) * 4 + 3 * CH_BYTES;
    cudaFuncSetAttribute(cin_fused, cudaFuncAttributeMaxDynamicSharedMemorySize, smemF);

    // Prep
    k_xT<<<(CIN_M * CIN_F0 + 255) / 256, 256>>>(x, xT);
    k_wp<<<1024, 256>>>(W0, wp_0, 64);
    k_wp<<<2048, 256>>>(W1, wp_1, 128);
    k_wp<<<2048, 256>>>(W2, wp_2, 128);

    // Fused 3-layer GEMM + reduction (grid = 256 tiles)
    cin_fused<<<CIN_M / 128, 256, smemF>>>(xT, wp_0, wp_1, wp_2, out);
}